// round 1
// baseline (speedup 1.0000x reference)
#include <cuda_runtime.h>

#define NMAX 10000
#define EMAX 640000
#define D 128

// ---- scratch (no allocations allowed) ----
__device__ int   g_is64;
__device__ int   g_count[NMAX];
__device__ int   g_rowptr[NMAX + 1];
__device__ int   g_cursor[NMAX];
__device__ int   g_cols[EMAX];
__device__ float g_y[(size_t)NMAX * D];   // agg_x / clamp(count)
__device__ float g_bflag[NMAX];           // 1 if in-degree > 0

__device__ __forceinline__ int load_idx(const void* ei, long long i, int is64) {
    if (is64) return (int)((const long long*)ei)[i];
    return ((const int*)ei)[i];
}

// K0: zero counts + detect int32 vs int64 edge_index on-device.
// If data is int64 (little-endian), odd 32-bit words are the high halves of
// values < 10000 -> all zero. If int32, odd words are random indices in
// [0,10000): P(all 32 probes zero) ~ 1e-128. Probe stays within first 256 B
// (valid for both layouts).
__global__ void k0_init(const void* ei, int n) {
    int t = blockIdx.x * blockDim.x + threadIdx.x;
    if (t < n) g_count[t] = 0;
    if (t == 0) {
        const int* w = (const int*)ei;
        int all0 = 1;
        #pragma unroll
        for (int i = 1; i < 64; i += 2) all0 &= (w[i] == 0);
        g_is64 = all0;
    }
}

// K1: in-degree histogram
__global__ void k1_count(const void* ei, int E) {
    int e = blockIdx.x * blockDim.x + threadIdx.x;
    if (e >= E) return;
    int r = load_idx(ei, e, g_is64);
    atomicAdd(&g_count[r], 1);
}

// K2: single-block exclusive scan over counts -> row_ptr (+ cursor copy)
__global__ void k2_scan(int n) {
    __shared__ int s[1024];
    const int PER = 10;                 // 1024*10 = 10240 >= NMAX
    int t = threadIdx.x;
    int base = t * PER;
    int loc[PER];
    int sum = 0;
    #pragma unroll
    for (int i = 0; i < PER; i++) {
        int idx = base + i;
        int v = (idx < n) ? g_count[idx] : 0;
        loc[i] = sum;
        sum += v;
    }
    s[t] = sum;
    __syncthreads();
    for (int off = 1; off < 1024; off <<= 1) {
        int v = (t >= off) ? s[t - off] : 0;
        __syncthreads();
        s[t] += v;
        __syncthreads();
    }
    int excl = s[t] - sum;              // exclusive prefix of thread totals
    #pragma unroll
    for (int i = 0; i < PER; i++) {
        int idx = base + i;
        if (idx < n) {
            int v = excl + loc[i];
            g_rowptr[idx] = v;
            g_cursor[idx] = v;
        }
    }
    if (t == blockDim.x - 1) g_rowptr[n] = s[t];
}

// K3: scatter col indices into CSR order
__global__ void k3_fill(const void* ei, int E) {
    int e = blockIdx.x * blockDim.x + threadIdx.x;
    if (e >= E) return;
    int is64 = g_is64;
    int r = load_idx(ei, e, is64);
    int c = load_idx(ei, (long long)E + e, is64);
    int pos = atomicAdd(&g_cursor[r], 1);
    g_cols[pos] = c;
}

// K4: one warp per node: sum x[col] over CSR neighbor list, divide by degree.
// Lane l owns float4 chunk l of the 128-float row (512B coalesced per edge).
// Col indices prefetched 32-at-a-time and broadcast via shfl.
__global__ void k4_gather(const float* __restrict__ x, int n) {
    int lane = threadIdx.x & 31;
    int node = blockIdx.x * (blockDim.x >> 5) + (threadIdx.x >> 5);
    if (node >= n) return;
    int s = g_rowptr[node];
    int e = g_rowptr[node + 1];
    const float4* x4 = (const float4*)x;
    float ax = 0.f, ay = 0.f, az = 0.f, aw = 0.f;

    int base = s;
    for (; base + 32 <= e; base += 32) {
        int c = g_cols[base + lane];
        #pragma unroll
        for (int j = 0; j < 32; j++) {
            int cj = __shfl_sync(0xffffffffu, c, j);
            float4 v = x4[(size_t)cj * 32 + lane];
            ax += v.x; ay += v.y; az += v.z; aw += v.w;
        }
    }
    if (base < e) {
        int m = e - base;
        int c = (lane < m) ? g_cols[base + lane] : 0;
        for (int j = 0; j < m; j++) {
            int cj = __shfl_sync(0xffffffffu, c, j);
            float4 v = x4[(size_t)cj * 32 + lane];
            ax += v.x; ay += v.y; az += v.z; aw += v.w;
        }
    }

    int deg = e - s;
    float scale = (deg > 0) ? (1.0f / (float)deg) : 0.0f;
    float4 r;
    r.x = ax * scale; r.y = ay * scale; r.z = az * scale; r.w = aw * scale;
    ((float4*)g_y)[(size_t)node * 32 + lane] = r;
    if (lane == 0) g_bflag[node] = (deg > 0) ? 1.0f : 0.0f;
}

// K5: fused dual GEMM epilogue:
//   out[n][j] = sum_k x[n][k]*Ws[j][k] + sum_k y[n][k]*Wn[j][k]
//              + b_self[j] + bflag[n]*b_neigh[j]
// 32-node tile in smem, thread j = output column, float4 over k.
__global__ void __launch_bounds__(128) k5_gemm(
    const float* __restrict__ x,
    const float* __restrict__ Ws, const float* __restrict__ bs,
    const float* __restrict__ Wn, const float* __restrict__ bn,
    float* __restrict__ out, int n)
{
    __shared__ float xs[32][D];
    __shared__ float ys[32][D];
    __shared__ float sb[32];
    int n0 = blockIdx.x * 32;
    int nb = min(32, n - n0);
    int tid = threadIdx.x;

    const float4* x4 = (const float4*)x;
    const float4* y4 = (const float4*)g_y;
    float4 z4 = make_float4(0.f, 0.f, 0.f, 0.f);
    for (int i = tid; i < 32 * 32; i += 128) {   // 32 rows x 32 float4
        int r = i >> 5;
        bool ok = r < nb;
        ((float4*)xs)[i] = ok ? x4[(size_t)(n0 + r) * 32 + (i & 31)] : z4;
        ((float4*)ys)[i] = ok ? y4[(size_t)(n0 + r) * 32 + (i & 31)] : z4;
    }
    if (tid < 32) sb[tid] = (tid < nb) ? g_bflag[n0 + tid] : 0.f;
    __syncthreads();

    int j = tid;
    float acc[32];
    #pragma unroll
    for (int i = 0; i < 32; i++) acc[i] = 0.f;

    for (int k = 0; k < D; k += 4) {
        float4 ws = *(const float4*)&Ws[j * D + k];
        float4 wn = *(const float4*)&Wn[j * D + k];
        #pragma unroll
        for (int nn = 0; nn < 32; nn++) {
            float4 xv = *(const float4*)&xs[nn][k];
            float4 yv = *(const float4*)&ys[nn][k];
            acc[nn] += ws.x * xv.x + ws.y * xv.y + ws.z * xv.z + ws.w * xv.w
                     + wn.x * yv.x + wn.y * yv.y + wn.z * yv.z + wn.w * yv.w;
        }
    }

    float bsj = bs[j], bnj = bn[j];
    for (int nn = 0; nn < nb; nn++) {
        out[(size_t)(n0 + nn) * D + j] = acc[nn] + bsj + sb[nn] * bnj;
    }
}

extern "C" void kernel_launch(void* const* d_in, const int* in_sizes, int n_in,
                              void* d_out, int out_size) {
    const float* x  = (const float*)d_in[0];
    const void*  ei = d_in[1];
    const float* Ws = (const float*)d_in[2];
    const float* bs = (const float*)d_in[3];
    const float* Wn = (const float*)d_in[4];
    const float* bn = (const float*)d_in[5];
    float* out = (float*)d_out;

    int N = in_sizes[0] / D;
    int E = in_sizes[1] / 2;
    if (N > NMAX) N = NMAX;
    if (E > EMAX) E = EMAX;

    k0_init <<<(N + 255) / 256, 256>>>(ei, N);
    k1_count<<<(E + 255) / 256, 256>>>(ei, E);
    k2_scan <<<1, 1024>>>(N);
    k3_fill <<<(E + 255) / 256, 256>>>(ei, E);
    k4_gather<<<(N + 7) / 8, 256>>>(x, N);
    k5_gemm <<<(N + 31) / 32, 128>>>(x, Ws, bs, Wn, bn, out, N);
}